// round 11
// baseline (speedup 1.0000x reference)
#include <cuda_runtime.h>

// KANN_31379031064675 — 2-layer LagrangeKANN.
// Occupancy play: 2 CTAs/SM x 640 threads (40 warps/SM vs 28).
//   Table SMEM per CTA = 112.25 KB: layer-1 compact Lagrange float2 (49.4 KB,
//   idx = node*32 + pair), layer-2 monomial float4 (64 KB, idx = e*64 + k).
// Task = 8 samples x 64 widths; 4 lanes per sample (chunk c = lane>>3), each
// lane runs 8 width-pairs (w = 8c + perm, pair (w, w+32)); shfl_xor(8,16)
// reduction; lanes 0-7 store. 16384 tasks, cyclic over 5920 warps.
// Element floor via saturate-magic (validated R8):
//   s  = saturate(fma(t, 64/63, -0.5/63)); y = asm fma(s, 63, 2^23)
//   e  = bits(y) & 63 (in-bounds);  xt = fma(t, 128, fma(y, -2, 2^24-1))

#define FULL_MASK 0xffffffffu

__device__ __forceinline__ float magic_fma(float s) {
    float y;
    asm("fma.rn.f32 %0, %1, %2, %3;" : "=f"(y)
        : "f"(s), "f"(63.0f), "f"(8388608.0f));
    return y;
}

__global__ void __launch_bounds__(640, 2) kann_kernel(
    const float* __restrict__ x,
    const float* __restrict__ w_inner,
    const float* __restrict__ w_outer,
    float* __restrict__ out, int n)
{
    extern __shared__ float smem[];
    float2* T1v = (float2*)smem;      // idx = node*32 + p  -> {W[p][node], W[p+32][node]}
    float*  T2f = smem + 12352;       // float4 idx = e*64 + k
    float*  S   = smem + 12352;       // staging scratch (16384 >= 12352)

    const int tid = threadIdx.x;
    const int nt = blockDim.x;

    // ---------------- build ----------------
    for (int f = tid; f < 12352; f += nt) S[f] = w_inner[f];
    __syncthreads();
    for (int idx = tid; idx < 6176; idx += nt) {   // compact T1 (raw weights)
        int node = idx >> 5, p = idx & 31;
        T1v[idx] = make_float2(S[p * 193 + node], S[(p + 32) * 193 + node]);
    }
    __syncthreads();
    for (int f = tid; f < 12352; f += nt) S[f] = w_outer[f];
    __syncthreads();
    // layer-2 monomial conversion (u_j = c_j W_j, c = {-9/16,27/16,-27/16,9/16})
    float a[7][4];
    #pragma unroll
    for (int r = 0; r < 7; ++r) {
        int f = tid + r * nt;
        if (f < 4096) {
            int k = f & 63, e = f >> 6;
            const float* wp = S + k * 193 + 3 * e;
            float u0 = -0.5625f * wp[0], u1 = 1.6875f * wp[1];
            float u2 = -1.6875f * wp[2], u3 = 0.5625f * wp[3];
            a[r][3] = (u0 + u1) + (u2 + u3);
            a[r][2] = (u3 - u0) + (1.0f / 3.0f) * (u2 - u1);
            a[r][1] = -(u1 + u2) - (1.0f / 9.0f) * (u0 + u3);
            a[r][0] = (1.0f / 3.0f) * (u1 - u2) + (1.0f / 9.0f) * (u0 - u3);
        }
    }
    __syncthreads();
    #pragma unroll
    for (int r = 0; r < 7; ++r) {
        int f = tid + r * nt;
        if (f < 4096) {
            int k = f & 63, e = f >> 6;
            ((float4*)T2f)[e * 64 + k] = make_float4(a[r][0], a[r][1], a[r][2], a[r][3]);
        }
    }
    __syncthreads();

    // ---------------- main ----------------
    const char* __restrict__ T1p = (const char*)smem;
    const char* __restrict__ T2p = (const char*)(smem + 12352);

    const int lane = tid & 31;
    const int wid = tid >> 5;
    const int sidx = lane & 7;          // sample slot within task
    const int c8 = (lane >> 3) << 3;    // width chunk * 8
    const int nwarp = gridDim.x * (nt >> 5);
    const int gwarp = blockIdx.x * (nt >> 5) + wid;
    const int ntasks = n >> 3;          // 16384 tasks of 8 samples

    for (int t = gwarp; t < ntasks; t += nwarp) {
        const int base = t << 3;
        const float xv = x[base + sidx];

        // per-task layer-1 params (sample fixed per lane)
        const float s1 = __saturatef(fmaf(xv, 64.0f / 63.0f, -0.5f / 63.0f));
        const float y1 = magic_fma(s1);
        const int nb = (__float_as_int(y1) & 63) * 768;  // byte offset of node 3e
        const float xt = fmaf(xv, 128.0f, fmaf(y1, -2.0f, 16777215.0f));

        // Lagrange basis (constants folded here; table holds raw weights)
        const float pp = xt + 1.0f;
        const float qq = xt + (1.0f / 3.0f);
        const float rr = xt - (1.0f / 3.0f);
        const float ss = xt - 1.0f;
        const float rs = rr * ss, pq = pp * qq;
        const float ph0 = -0.5625f * (qq * rs);
        const float ph1 =  1.6875f * (pp * rs);
        const float ph2 = -1.6875f * (pq * ss);
        const float ph3 =  0.5625f * (pq * rr);

        float accA = 0.0f, accB = 0.0f;
        #pragma unroll 4
        for (int i = 0; i < 8; ++i) {
            const int w = ((sidx + i) & 7) | c8;
            const int wb8 = w << 3, wb16 = w << 4;

            // layer 1: 4 LDS.64 (banks 2w mod 32, conflict-free) + 8 FMA
            const float2 w0 = *(const float2*)(T1p + nb + wb8);
            const float2 w1 = *(const float2*)(T1p + nb + 256 + wb8);
            const float2 w2 = *(const float2*)(T1p + nb + 512 + wb8);
            const float2 w3 = *(const float2*)(T1p + nb + 768 + wb8);
            const float tA = fmaf(ph3, w3.x, fmaf(ph2, w2.x, fmaf(ph1, w1.x, ph0 * w0.x)));
            const float tB = fmaf(ph3, w3.y, fmaf(ph2, w2.y, fmaf(ph1, w1.y, ph0 * w0.y)));

            // layer 2, width w
            const float sA = __saturatef(fmaf(tA, 64.0f / 63.0f, -0.5f / 63.0f));
            const float yA = magic_fma(sA);
            const int eAb = (__float_as_int(yA) & 63) << 10;
            const float xtA = fmaf(tA, 128.0f, fmaf(yA, -2.0f, 16777215.0f));
            const float4 dA = *(const float4*)(T2p + eAb + wb16);
            accA += fmaf(fmaf(fmaf(dA.w, xtA, dA.z), xtA, dA.y), xtA, dA.x);

            // layer 2, width w+32
            const float sB = __saturatef(fmaf(tB, 64.0f / 63.0f, -0.5f / 63.0f));
            const float yB = magic_fma(sB);
            const int eBb = (__float_as_int(yB) & 63) << 10;
            const float xtB = fmaf(tB, 128.0f, fmaf(yB, -2.0f, 16777215.0f));
            const float4 dB = *(const float4*)(T2p + eBb + 512 + wb16);
            accB += fmaf(fmaf(fmaf(dB.w, xtB, dB.z), xtB, dB.y), xtB, dB.x);
        }

        // combine the 4 lane-chunks of each sample
        float rsum = accA + accB;
        rsum += __shfl_xor_sync(FULL_MASK, rsum, 8);
        rsum += __shfl_xor_sync(FULL_MASK, rsum, 16);
        if (lane < 8) out[base + lane] = rsum;
    }
}

extern "C" void kernel_launch(void* const* d_in, const int* in_sizes, int n_in,
                              void* d_out, int out_size) {
    const float* x  = (const float*)d_in[0];
    const float* wi = (const float*)d_in[1];
    const float* wo = (const float*)d_in[2];
    float* out = (float*)d_out;
    const int n = in_sizes[0];

    const int smem_bytes = 28736 * sizeof(float);  // 112.25 KB -> 2 CTAs/SM
    cudaFuncSetAttribute(kann_kernel, cudaFuncAttributeMaxDynamicSharedMemorySize,
                         smem_bytes);
    kann_kernel<<<296, 640, smem_bytes>>>(x, wi, wo, out, n);
}

// round 13
// speedup vs baseline: 1.2495x; 1.2495x over previous
#include <cuda_runtime.h>
#include <cuda_fp16.h>

// KANN_31379031064675 — 2-layer LagrangeKANN.
// Lane owns one sample per 32-group; walks width pairs (w, w+32), 32 iters.
// BOTH tables monomial cubic.
//   T1: float4 {a0,a1,a2,a3}, idx = e*64 + k (64 KB)       -> LDS.128
//   T2: split precision, 12 B/width:
//       T2a float2 {a0',a1'} (32 KB), T2b half2 {a2,a3} (16 KB)
//       with Chebyshev compensation: a0' = a0 + (a2-h2)/2, a1' = a1 + 3/4(a3-h3)
// Element floor via saturate-magic (validated R8):
//   s = saturate(fma(t, 64/63, -0.5/63)); y = asm fma(s, 63, 2^23)
//   e = bits(y) & 63 (in-bounds);  xt = fma(t, 128, fma(y, -2, 2^24-1))

__device__ __forceinline__ float magic_fma(float s) {
    float y;
    asm("fma.rn.f32 %0, %1, %2, %3;" : "=f"(y)
        : "f"(s), "f"(63.0f), "f"(8388608.0f));
    return y;
}

__global__ void __launch_bounds__(896, 1) kann_kernel(
    const float* __restrict__ x,
    const float* __restrict__ w_inner,
    const float* __restrict__ w_outer,
    float* __restrict__ out, int n)
{
    extern __shared__ float smem[];
    float*   T1f = smem;                        // float4 idx = e*64 + k
    float*   T2a = smem + 16384;                // float2 idx = e*64 + k  {a0',a1'}
    __half2* T2b = (__half2*)(smem + 24576);    // half2  idx = e*64 + k  {a2,a3}
    float*   SB  = smem + 16384;                // staging (12352 <= 12352+pad)

    const int tid = threadIdx.x;
    const int nt = blockDim.x;

    // ---------------- build ----------------
    // monomial conversion: u_j = c_j W_j, c = {-9/16, 27/16, -27/16, 9/16}
    //   a3 = u0+u1+u2+u3 ; a2 = (u3-u0)+(u2-u1)/3
    //   a1 = -(u1+u2)-(u0+u3)/9 ; a0 = (u1-u2)/3+(u0-u3)/9

    // layer 1: stage w_inner -> SB, then convert directly into T1 (disjoint regions)
    for (int f = tid; f < 12352; f += nt) SB[f] = w_inner[f];
    __syncthreads();
    for (int f = tid; f < 4096; f += nt) {
        int k = f & 63, e = f >> 6;
        const float* wp = SB + k * 193 + 3 * e;
        float u0 = -0.5625f * wp[0], u1 = 1.6875f * wp[1];
        float u2 = -1.6875f * wp[2], u3 = 0.5625f * wp[3];
        float a3 = (u0 + u1) + (u2 + u3);
        float a2 = (u3 - u0) + (1.0f / 3.0f) * (u2 - u1);
        float a1 = -(u1 + u2) - (1.0f / 9.0f) * (u0 + u3);
        float a0 = (1.0f / 3.0f) * (u1 - u2) + (1.0f / 9.0f) * (u0 - u3);
        ((float4*)T1f)[f] = make_float4(a0, a1, a2, a3);
    }
    __syncthreads();
    // layer 2: stage w_outer -> SB (overlaps T2 output: two-phase via registers)
    for (int f = tid; f < 12352; f += nt) SB[f] = w_outer[f];
    __syncthreads();
    float a[5][4];
    #pragma unroll
    for (int r = 0; r < 5; ++r) {
        int f = tid + r * nt;
        if (f < 4096) {
            int k = f & 63, e = f >> 6;
            const float* wp = SB + k * 193 + 3 * e;
            float u0 = -0.5625f * wp[0], u1 = 1.6875f * wp[1];
            float u2 = -1.6875f * wp[2], u3 = 0.5625f * wp[3];
            a[r][3] = (u0 + u1) + (u2 + u3);
            a[r][2] = (u3 - u0) + (1.0f / 3.0f) * (u2 - u1);
            a[r][1] = -(u1 + u2) - (1.0f / 9.0f) * (u0 + u3);
            a[r][0] = (1.0f / 3.0f) * (u1 - u2) + (1.0f / 9.0f) * (u0 - u3);
        }
    }
    __syncthreads();
    #pragma unroll
    for (int r = 0; r < 5; ++r) {
        int f = tid + r * nt;
        if (f < 4096) {
            float a0 = a[r][0], a1 = a[r][1], a2 = a[r][2], a3 = a[r][3];
            __half h2 = __float2half_rn(a2);
            __half h3 = __float2half_rn(a3);
            float r2 = a2 - __half2float(h2);
            float r3 = a3 - __half2float(h3);
            // Chebyshev folding of residuals: xt^2 ~ 1/2, xt^3 ~ (3/4)xt
            ((float2*)T2a)[f] = make_float2(a0 + 0.5f * r2, fmaf(0.75f, r3, a1));
            T2b[f] = __halves2half2(h2, h3);
        }
    }
    __syncthreads();

    // ---------------- main ----------------
    const char* __restrict__ T1p  = (const char*)T1f;
    const char* __restrict__ T2ap = (const char*)T2a;
    const __half2* __restrict__ T2bp = T2b;

    const int lane = tid & 31;
    const int wid = tid >> 5;
    const int nwarp = gridDim.x * (nt >> 5);
    const int gwarp = wid * gridDim.x + blockIdx.x;
    const int ngroups = n >> 5;

    for (int g = gwarp; g < ngroups; g += nwarp) {
        const int base = g << 5;
        const float xv = x[base + lane];

        // per-group layer-1 params
        const float s1 = __saturatef(fmaf(xv, 64.0f / 63.0f, -0.5f / 63.0f));
        const float y1 = magic_fma(s1);
        const int b1 = (__float_as_int(y1) & 63) << 10;   // byte offset, in-bounds
        const float xt = fmaf(xv, 128.0f, fmaf(y1, -2.0f, 16777215.0f));

        float accA = 0.0f, accB = 0.0f;

        #pragma unroll 4
        for (int i = 0; i < 32; ++i) {
            const int w = (lane + i) & 31;

            // layer 1: 2 LDS.128 + 6 FMA (shared xt), widths (w, w+32)
            const float4 cA = *(const float4*)(T1p + b1 + (w << 4));
            const float4 cB = *(const float4*)(T1p + b1 + 512 + (w << 4));
            const float tA = fmaf(fmaf(fmaf(cA.w, xt, cA.z), xt, cA.y), xt, cA.x);
            const float tB = fmaf(fmaf(fmaf(cB.w, xt, cB.z), xt, cB.y), xt, cB.x);

            // layer 2, width w: 8B fp32 {a0',a1'} + 4B half2 {a2,a3}
            const float sA = __saturatef(fmaf(tA, 64.0f / 63.0f, -0.5f / 63.0f));
            const float yA = magic_fma(sA);
            const int eA = __float_as_int(yA) & 63;
            const float xtA = fmaf(tA, 128.0f, fmaf(yA, -2.0f, 16777215.0f));
            const float2 abA = *(const float2*)(T2ap + (eA << 9) + (w << 3));
            const float2 cdA = __half22float2(T2bp[(eA << 6) + w]);
            accA += fmaf(fmaf(fmaf(cdA.y, xtA, cdA.x), xtA, abA.y), xtA, abA.x);

            // layer 2, width w+32
            const float sB = __saturatef(fmaf(tB, 64.0f / 63.0f, -0.5f / 63.0f));
            const float yB = magic_fma(sB);
            const int eB = __float_as_int(yB) & 63;
            const float xtB = fmaf(tB, 128.0f, fmaf(yB, -2.0f, 16777215.0f));
            const float2 abB = *(const float2*)(T2ap + (eB << 9) + 256 + (w << 3));
            const float2 cdB = __half22float2(T2bp[(eB << 6) + 32 + w]);
            accB += fmaf(fmaf(fmaf(cdB.y, xtB, cdB.x), xtB, abB.y), xtB, abB.x);
        }
        out[base + lane] = accA + accB;
    }
}

extern "C" void kernel_launch(void* const* d_in, const int* in_sizes, int n_in,
                              void* d_out, int out_size) {
    const float* x  = (const float*)d_in[0];
    const float* wi = (const float*)d_in[1];
    const float* wo = (const float*)d_in[2];
    float* out = (float*)d_out;
    const int n = in_sizes[0];

    const int smem_bytes = 28736 * sizeof(float);  // 112.25 KB
    cudaFuncSetAttribute(kann_kernel, cudaFuncAttributeMaxDynamicSharedMemorySize,
                         smem_bytes);
    kann_kernel<<<148, 896, smem_bytes>>>(x, wi, wo, out, n);
}